// round 6
// baseline (speedup 1.0000x reference)
#include <cuda_runtime.h>

#define B_  4
#define M_  256
#define N_  256
#define L_  24
#define S_  22
#define NL1 279          // N + L - 1
#define SW  23           // padded shot-stride (coprime with 32 banks)
#define NT  512

// ---------------------------------------------------------------------------
// Compile-time Gaussian color bases: f(l) = exp(-0.5*((wl-mu)/50)^2),
// wl = linspace(400,700,24). Computed in double at compile time; arrays are
// __device__ constexpr so device code can use them WITHOUT
// --expt-relaxed-constexpr, and unrolled constant-index accesses fold to FP32
// immediates => FFMA-imm (rt=1).
// ---------------------------------------------------------------------------
constexpr double cexp_neg(double y) {   // returns exp(-y), y >= 0 (no cancellation)
    double t = 1.0, term = 1.0;
    for (int k = 1; k < 120; k++) {
        term *= y / (double)k;
        t += term;
        if (term < t * 1e-30) break;    // converged; avoid constexpr underflow
    }
    return 1.0 / t;
}
constexpr float fband(int l, double mu) {
    double wl = 400.0 + 300.0 * (double)l / 23.0;
    double d  = (wl - mu) / 50.0;
    return (float)cexp_neg(0.5 * d * d);
}
#define B24(mu) { fband(0,mu),fband(1,mu),fband(2,mu),fband(3,mu),fband(4,mu),fband(5,mu), \
                  fband(6,mu),fband(7,mu),fband(8,mu),fband(9,mu),fband(10,mu),fband(11,mu), \
                  fband(12,mu),fband(13,mu),fband(14,mu),fband(15,mu),fband(16,mu),fband(17,mu), \
                  fband(18,mu),fband(19,mu),fband(20,mu),fband(21,mu),fband(22,mu),fband(23,mu) }

// pairing per reference: wr<->g(620), wg<->g(550), wb<->g(450), wc<->g(500)
__device__ constexpr float FR[24] = B24(620.0);
__device__ constexpr float FG[24] = B24(550.0);
__device__ constexpr float FB[24] = B24(450.0);
__device__ constexpr float FC[24] = B24(500.0);

__device__ int g_maxbits;   // global max of X as int bits (all X >= 0)

__global__ void cassi_init() { g_maxbits = 0; }

// SMEM layout (floats):
//   wsm : 4 * 256 * SW  = 23552   (w_c[m,n,s] / wt, padded stride SW)
//   xsm : 256 * 24      = 6144    (x row; reused as X-partial scratch in pass 2)
//   ysm : 279 * SW      = 6417
#define WSM_F (4 * 256 * SW)
#define XSM_F (N_ * L_)
#define YSM_F (NL1 * SW)
#define SMEM_FLOATS (WSM_F + XSM_F + YSM_F)
#define SMEM_BYTES  (SMEM_FLOATS * 4)

__global__ void __launch_bounds__(NT, 1) cassi_main(
    const float* __restrict__ xg,
    const float* __restrict__ wr, const float* __restrict__ wg,
    const float* __restrict__ wb, const float* __restrict__ wc,
    float* __restrict__ out)
{
    extern __shared__ float sm[];
    float* wsm = sm;
    float* xsm = wsm + WSM_F;
    float* ysm = xsm + XSM_F;

    const int tid = threadIdx.x;
    const int m   = blockIdx.x & (M_ - 1);
    const int b   = blockIdx.x >> 8;

    // ---- load weights, pre-normalize by wt --------------------------------
    {
        const int base = m * (N_ * S_);
        for (int i = tid; i < N_ * S_; i += NT) {
            float r = wr[base + i], g = wg[base + i];
            float u = wb[base + i], v = wc[base + i];
            float inv = 1.0f / (r + g + u + v);
            int n = i / S_, s = i - n * S_;
            int o = n * SW + s;
            wsm[o]                = r * inv;
            wsm[256 * SW + o]     = g * inv;
            wsm[2 * 256 * SW + o] = u * inv;
            wsm[3 * 256 * SW + o] = v * inv;
        }
    }
    // ---- load x row (vectorized) ------------------------------------------
    {
        const float4* xg4 = (const float4*)(xg + (size_t)(b * M_ + m) * (N_ * L_));
        float4* xs4 = (float4*)xsm;
        for (int i = tid; i < (N_ * L_) / 4; i += NT) xs4[i] = xg4[i];
    }
    // ---- zero Y ------------------------------------------------------------
    for (int i = tid; i < NL1 * SW; i += NT) ysm[i] = 0.0f;
    __syncthreads();

    // ======================= Pass 1: Y (shift & sum) =========================
    // thread = (shot s, chunk of 12 source columns). Register sliding window.
    if (tid < S_ * 23) {
        const int s     = tid % S_;
        const int chunk = tid / S_;
        const int n0    = chunk * 12;
        if (n0 < N_) {
            const int n1 = min(n0 + 12, N_);
            const float* w0 = wsm + s;
            float Yw[24];
            #pragma unroll
            for (int l = 0; l < 24; l++) Yw[l] = 0.0f;

            for (int n = n0; n < n1; n++) {
                const float pr = w0[n * SW];
                const float pg = w0[256 * SW + n * SW];
                const float pb = w0[2 * 256 * SW + n * SW];
                const float pc = w0[3 * 256 * SW + n * SW];
                const float* xr = xsm + n * L_;
                #pragma unroll
                for (int l = 0; l < 24; l++) {
                    float h = FR[l] * pr;                 // FMUL-imm
                    h = fmaf(FG[l], pg, h);               // FFMA-imm
                    h = fmaf(FB[l], pb, h);               // FFMA-imm
                    h = fmaf(FC[l], pc, h);               // FFMA-imm
                    Yw[l] = fmaf(xr[l], h, Yw[l]);        // FFMA
                }
                atomicAdd(&ysm[n * SW + s], Yw[0]);
                #pragma unroll
                for (int l = 0; l < 23; l++) Yw[l] = Yw[l + 1];
                Yw[23] = 0.0f;
            }
            // flush tail: Yw[j] holds partial of Y[n1 + j]
            #pragma unroll
            for (int j = 0; j < 23; j++)
                atomicAdd(&ysm[(n1 + j) * SW + s], Yw[j]);
        }
    }
    __syncthreads();

    // ================= Pass 2: X (adjoint re-code, sum over s) ==============
    // 512 threads: thread = (column n, half of the shots)
    {
        const int n   = tid & 255;
        const int grp = tid >> 8;          // 0: s in [0,11), 1: s in [11,22)
        const int s0  = grp * 11;
        float Xa[24];
        #pragma unroll
        for (int l = 0; l < 24; l++) Xa[l] = 0.0f;

        const float* w0 = wsm + n * SW;
        for (int s = s0; s < s0 + 11; s++) {
            const float pr = w0[s];
            const float pg = w0[256 * SW + s];
            const float pb = w0[2 * 256 * SW + s];
            const float pc = w0[3 * 256 * SW + s];
            const float* yr = ysm + n * SW + s;
            #pragma unroll
            for (int l = 0; l < 24; l++) {
                float h = FR[l] * pr;
                h = fmaf(FG[l], pg, h);
                h = fmaf(FB[l], pb, h);
                h = fmaf(FC[l], pc, h);
                Xa[l] = fmaf(h, yr[l * SW], Xa[l]);
            }
        }
        __syncthreads();                   // x row no longer needed; reuse as scratch
        if (grp == 1) {
            float* xp = xsm + n * L_;
            #pragma unroll
            for (int l = 0; l < 24; l++) xp[l] = Xa[l];
        }
        __syncthreads();
        if (grp == 0) {
            const float* xp = xsm + n * L_;
            float vv[24];
            float mx = 0.0f;
            #pragma unroll
            for (int l = 0; l < 24; l++) {
                vv[l] = Xa[l] + xp[l];
                mx = fmaxf(mx, vv[l]);
            }
            float4* o4 = (float4*)(out + (((size_t)(b * M_ + m) * N_) + n) * L_);
            #pragma unroll
            for (int q = 0; q < 6; q++)
                o4[q] = make_float4(vv[4 * q], vv[4 * q + 1], vv[4 * q + 2], vv[4 * q + 3]);
            // block/global max (all values >= 0 -> int-bit compare valid)
            #pragma unroll
            for (int o = 16; o > 0; o >>= 1)
                mx = fmaxf(mx, __shfl_xor_sync(0xffffffffu, mx, o));
            if ((tid & 31) == 0) atomicMax(&g_maxbits, __float_as_int(mx));
        }
    }
}

__global__ void cassi_norm(float* __restrict__ out, int ntotal4)
{
    const int i = blockIdx.x * blockDim.x + threadIdx.x;
    const float inv = 1.0f / __int_as_float(g_maxbits);
    if (i < ntotal4) {
        float4* o = (float4*)out;
        float4 v = o[i];
        v.x *= inv; v.y *= inv; v.z *= inv; v.w *= inv;
        o[i] = v;
    }
}

extern "C" void kernel_launch(void* const* d_in, const int* in_sizes, int n_in,
                              void* d_out, int out_size)
{
    const float* x  = (const float*)d_in[0];
    const float* wr = (const float*)d_in[1];
    const float* wg = (const float*)d_in[2];
    const float* wb = (const float*)d_in[3];
    const float* wc = (const float*)d_in[4];
    float* out = (float*)d_out;

    cudaFuncSetAttribute(cassi_main, cudaFuncAttributeMaxDynamicSharedMemorySize, SMEM_BYTES);

    cassi_init<<<1, 1>>>();
    cassi_main<<<B_ * M_, NT, SMEM_BYTES>>>(x, wr, wg, wb, wc, out);

    const int ntotal4 = (B_ * M_ * N_ * L_) / 4;     // 1,572,864
    cassi_norm<<<(ntotal4 + 255) / 256, 256>>>(out, ntotal4);
}